// round 1
// baseline (speedup 1.0000x reference)
#include <cuda_runtime.h>
#include <cstdint>

#define BB 4
#define CC 512
#define HWN 4096
#define NG 32
#define CPG 16
#define QK_SCALE 0.044194173824159216f  // 1/sqrt(512)

// ---------------- static scratch (no allocations allowed) ----------------
__device__ float g_h[(size_t)BB * CC * HWN];   // groupnorm output
__device__ float g_q[(size_t)BB * CC * HWN];
__device__ float g_k[(size_t)BB * CC * HWN];
__device__ float g_v[(size_t)BB * CC * HWN];
__device__ float g_s[(size_t)BB * HWN * HWN];  // scores / attn (256 MB)
__device__ float g_o[(size_t)BB * CC * HWN];   // attn @ V

// ---------------- GroupNorm ----------------
__global__ __launch_bounds__(256) void gn_kernel(const float* __restrict__ x,
                                                 const float* __restrict__ gamma,
                                                 const float* __restrict__ beta) {
    int b = blockIdx.x / NG, g = blockIdx.x % NG;
    const float* xp = x + ((size_t)b * CC + (size_t)g * CPG) * HWN;
    float* hp = g_h + ((size_t)b * CC + (size_t)g * CPG) * HWN;
    const int n = CPG * HWN;  // 65536

    float s = 0.f, s2 = 0.f;
    for (int i = threadIdx.x * 4; i < n; i += 1024) {
        float4 v = *(const float4*)&xp[i];
        s  += v.x + v.y + v.z + v.w;
        s2 += v.x * v.x + v.y * v.y + v.z * v.z + v.w * v.w;
    }
    __shared__ float rs[256], rs2[256];
    rs[threadIdx.x] = s; rs2[threadIdx.x] = s2;
    __syncthreads();
    for (int st = 128; st > 0; st >>= 1) {
        if (threadIdx.x < st) {
            rs[threadIdx.x]  += rs[threadIdx.x + st];
            rs2[threadIdx.x] += rs2[threadIdx.x + st];
        }
        __syncthreads();
    }
    float mean = rs[0] / n;
    float var  = rs2[0] / n - mean * mean;
    float inv  = rsqrtf(var + 1e-6f);

    for (int i = threadIdx.x * 4; i < n; i += 1024) {
        int c = g * CPG + (i >> 12);
        float ga = gamma[c], be = beta[c];
        float4 v = *(const float4*)&xp[i];
        float4 r;
        r.x = (v.x - mean) * inv * ga + be;
        r.y = (v.y - mean) * inv * ga + be;
        r.z = (v.z - mean) * inv * ga + be;
        r.w = (v.w - mean) * inv * ga + be;
        *(float4*)&hp[i] = r;
    }
}

// ---------------- shared GEMM compute core: 128x128x8, 8x8/thread ----------------
__device__ __forceinline__ void mm_compute(const float (&As)[8][132],
                                           const float (&Bs)[8][132],
                                           float (&acc)[8][8], int tx, int ty) {
#pragma unroll
    for (int k = 0; k < 8; k++) {
        float a[8], bb[8];
        *(float4*)(&a[0])  = *(const float4*)&As[k][ty * 4];
        *(float4*)(&a[4])  = *(const float4*)&As[k][64 + ty * 4];
        *(float4*)(&bb[0]) = *(const float4*)&Bs[k][tx * 4];
        *(float4*)(&bb[4]) = *(const float4*)&Bs[k][64 + tx * 4];
#pragma unroll
        for (int i = 0; i < 8; i++)
#pragma unroll
            for (int j = 0; j < 8; j++)
                acc[i][j] = fmaf(a[i], bb[j], acc[i][j]);
    }
}

// ---------------- QKV: OUT[o,n] = W[o,:] . H[:,n] + bias[o] ----------------
__global__ __launch_bounds__(256) void qkv_kernel(const float* __restrict__ wq, const float* __restrict__ bq,
                                                  const float* __restrict__ wk, const float* __restrict__ bk,
                                                  const float* __restrict__ wv, const float* __restrict__ bv) {
    int mz = blockIdx.z;
    int b = mz / 3, m = mz % 3;
    const float* W    = (m == 0) ? wq : (m == 1) ? wk : wv;
    const float* bias = (m == 0) ? bq : (m == 1) ? bk : bv;
    float* OUT = ((m == 0) ? g_q : (m == 1) ? g_k : g_v) + (size_t)b * CC * HWN;
    const float* IN = g_h + (size_t)b * CC * HWN;

    int o0 = blockIdx.y * 128;
    int n0 = blockIdx.x * 128;

    __shared__ __align__(16) float As[8][132];
    __shared__ __align__(16) float Bs[8][132];
    int tid = threadIdx.x, tx = tid % 16, ty = tid / 16;

    float acc[8][8];
#pragma unroll
    for (int i = 0; i < 8; i++)
#pragma unroll
        for (int j = 0; j < 8; j++) acc[i][j] = 0.f;

    int arow = tid >> 1, ak = (tid & 1) * 4;       // W tile: 128 rows(o) x 8(k)
    int brow = tid >> 5, bcol = (tid & 31) * 4;    // IN tile: 8 rows(k) x 128(n)

    for (int c0 = 0; c0 < CC; c0 += 8) {
        float4 wv4 = *(const float4*)&W[(size_t)(o0 + arow) * CC + c0 + ak];
        float4 iv4 = *(const float4*)&IN[(size_t)(c0 + brow) * HWN + n0 + bcol];
        __syncthreads();
        As[ak + 0][arow] = wv4.x; As[ak + 1][arow] = wv4.y;
        As[ak + 2][arow] = wv4.z; As[ak + 3][arow] = wv4.w;
        *(float4*)&Bs[brow][bcol] = iv4;
        __syncthreads();
        mm_compute(As, Bs, acc, tx, ty);
    }

#pragma unroll
    for (int i = 0; i < 8; i++) {
        int oo = (i < 4) ? (ty * 4 + i) : (64 + ty * 4 + i - 4);
        float bv_ = bias[o0 + oo];
        float4 r0 = make_float4(acc[i][0] + bv_, acc[i][1] + bv_, acc[i][2] + bv_, acc[i][3] + bv_);
        float4 r1 = make_float4(acc[i][4] + bv_, acc[i][5] + bv_, acc[i][6] + bv_, acc[i][7] + bv_);
        *(float4*)&OUT[(size_t)(o0 + oo) * HWN + n0 + tx * 4]      = r0;
        *(float4*)&OUT[(size_t)(o0 + oo) * HWN + n0 + 64 + tx * 4] = r1;
    }
}

// ---------------- scores: S[n,m] = scale * sum_c Q[c,n] K[c,m] ----------------
__global__ __launch_bounds__(256) void scores_kernel() {
    int b = blockIdx.z;
    const float* Q = g_q + (size_t)b * CC * HWN;
    const float* K = g_k + (size_t)b * CC * HWN;
    float* S = g_s + (size_t)b * HWN * HWN;
    int n0 = blockIdx.y * 128, m0 = blockIdx.x * 128;

    __shared__ __align__(16) float As[8][132];
    __shared__ __align__(16) float Bs[8][132];
    int tid = threadIdx.x, tx = tid % 16, ty = tid / 16;
    int lrow = tid >> 5, lcol = (tid & 31) * 4;

    float acc[8][8];
#pragma unroll
    for (int i = 0; i < 8; i++)
#pragma unroll
        for (int j = 0; j < 8; j++) acc[i][j] = 0.f;

    for (int c0 = 0; c0 < CC; c0 += 8) {
        float4 qa = *(const float4*)&Q[(size_t)(c0 + lrow) * HWN + n0 + lcol];
        float4 kb = *(const float4*)&K[(size_t)(c0 + lrow) * HWN + m0 + lcol];
        __syncthreads();
        *(float4*)&As[lrow][lcol] = qa;
        *(float4*)&Bs[lrow][lcol] = kb;
        __syncthreads();
        mm_compute(As, Bs, acc, tx, ty);
    }

#pragma unroll
    for (int i = 0; i < 8; i++) {
        int nn = (i < 4) ? (ty * 4 + i) : (64 + ty * 4 + i - 4);
        float4 r0 = make_float4(acc[i][0] * QK_SCALE, acc[i][1] * QK_SCALE,
                                acc[i][2] * QK_SCALE, acc[i][3] * QK_SCALE);
        float4 r1 = make_float4(acc[i][4] * QK_SCALE, acc[i][5] * QK_SCALE,
                                acc[i][6] * QK_SCALE, acc[i][7] * QK_SCALE);
        *(float4*)&S[(size_t)(n0 + nn) * HWN + m0 + tx * 4]      = r0;
        *(float4*)&S[(size_t)(n0 + nn) * HWN + m0 + 64 + tx * 4] = r1;
    }
}

// ---------------- softmax over last dim (4096), one block per row ----------------
__global__ __launch_bounds__(256) void softmax_kernel() {
    float* row = g_s + (size_t)blockIdx.x * HWN;
    int tid = threadIdx.x;

    float4 vals[4];
    float mx = -1e30f;
#pragma unroll
    for (int i = 0; i < 4; i++) {
        vals[i] = *(const float4*)&row[(i * 256 + tid) * 4];
        mx = fmaxf(mx, fmaxf(fmaxf(vals[i].x, vals[i].y), fmaxf(vals[i].z, vals[i].w)));
    }
    __shared__ float red[256];
    red[tid] = mx; __syncthreads();
    for (int st = 128; st > 0; st >>= 1) {
        if (tid < st) red[tid] = fmaxf(red[tid], red[tid + st]);
        __syncthreads();
    }
    mx = red[0];
    __syncthreads();

    float sum = 0.f;
#pragma unroll
    for (int i = 0; i < 4; i++) {
        vals[i].x = __expf(vals[i].x - mx);
        vals[i].y = __expf(vals[i].y - mx);
        vals[i].z = __expf(vals[i].z - mx);
        vals[i].w = __expf(vals[i].w - mx);
        sum += vals[i].x + vals[i].y + vals[i].z + vals[i].w;
    }
    red[tid] = sum; __syncthreads();
    for (int st = 128; st > 0; st >>= 1) {
        if (tid < st) red[tid] += red[tid + st];
        __syncthreads();
    }
    float inv = 1.0f / red[0];

#pragma unroll
    for (int i = 0; i < 4; i++) {
        vals[i].x *= inv; vals[i].y *= inv; vals[i].z *= inv; vals[i].w *= inv;
        *(float4*)&row[(i * 256 + tid) * 4] = vals[i];
    }
}

// ---------------- O[c,n] = sum_m V[c,m] * A[n,m] ----------------
__global__ __launch_bounds__(256) void av_kernel() {
    int b = blockIdx.z;
    const float* V = g_v + (size_t)b * CC * HWN;
    const float* A = g_s + (size_t)b * HWN * HWN;
    float* O = g_o + (size_t)b * CC * HWN;
    int c0 = blockIdx.y * 128, n0 = blockIdx.x * 128;

    __shared__ __align__(16) float As[8][132];  // V^T tile: [m][c]
    __shared__ __align__(16) float Bs[8][132];  // A^T tile: [m][n]
    int tid = threadIdx.x, tx = tid % 16, ty = tid / 16;
    int arow = tid >> 1, ak = (tid & 1) * 4;

    float acc[8][8];
#pragma unroll
    for (int i = 0; i < 8; i++)
#pragma unroll
        for (int j = 0; j < 8; j++) acc[i][j] = 0.f;

    for (int m0 = 0; m0 < HWN; m0 += 8) {
        float4 va = *(const float4*)&V[(size_t)(c0 + arow) * HWN + m0 + ak];
        float4 aa = *(const float4*)&A[(size_t)(n0 + arow) * HWN + m0 + ak];
        __syncthreads();
        As[ak + 0][arow] = va.x; As[ak + 1][arow] = va.y;
        As[ak + 2][arow] = va.z; As[ak + 3][arow] = va.w;
        Bs[ak + 0][arow] = aa.x; Bs[ak + 1][arow] = aa.y;
        Bs[ak + 2][arow] = aa.z; Bs[ak + 3][arow] = aa.w;
        __syncthreads();
        mm_compute(As, Bs, acc, tx, ty);
    }

#pragma unroll
    for (int i = 0; i < 8; i++) {
        int cc = (i < 4) ? (ty * 4 + i) : (64 + ty * 4 + i - 4);
        float4 r0 = make_float4(acc[i][0], acc[i][1], acc[i][2], acc[i][3]);
        float4 r1 = make_float4(acc[i][4], acc[i][5], acc[i][6], acc[i][7]);
        *(float4*)&O[(size_t)(c0 + cc) * HWN + n0 + tx * 4]      = r0;
        *(float4*)&O[(size_t)(c0 + cc) * HWN + n0 + 64 + tx * 4] = r1;
    }
}

// ---------------- proj + residual: out = x + Wp @ O + bp ----------------
__global__ __launch_bounds__(256) void proj_kernel(const float* __restrict__ wp,
                                                   const float* __restrict__ bp,
                                                   const float* __restrict__ x,
                                                   float* __restrict__ out) {
    int b = blockIdx.z;
    const float* IN = g_o + (size_t)b * CC * HWN;
    const float* XR = x + (size_t)b * CC * HWN;
    float* OUT = out + (size_t)b * CC * HWN;

    int o0 = blockIdx.y * 128, n0 = blockIdx.x * 128;

    __shared__ __align__(16) float As[8][132];
    __shared__ __align__(16) float Bs[8][132];
    int tid = threadIdx.x, tx = tid % 16, ty = tid / 16;
    int arow = tid >> 1, ak = (tid & 1) * 4;
    int brow = tid >> 5, bcol = (tid & 31) * 4;

    float acc[8][8];
#pragma unroll
    for (int i = 0; i < 8; i++)
#pragma unroll
        for (int j = 0; j < 8; j++) acc[i][j] = 0.f;

    for (int c0 = 0; c0 < CC; c0 += 8) {
        float4 wv4 = *(const float4*)&wp[(size_t)(o0 + arow) * CC + c0 + ak];
        float4 iv4 = *(const float4*)&IN[(size_t)(c0 + brow) * HWN + n0 + bcol];
        __syncthreads();
        As[ak + 0][arow] = wv4.x; As[ak + 1][arow] = wv4.y;
        As[ak + 2][arow] = wv4.z; As[ak + 3][arow] = wv4.w;
        *(float4*)&Bs[brow][bcol] = iv4;
        __syncthreads();
        mm_compute(As, Bs, acc, tx, ty);
    }

#pragma unroll
    for (int i = 0; i < 8; i++) {
        int oo = (i < 4) ? (ty * 4 + i) : (64 + ty * 4 + i - 4);
        float bv_ = bp[o0 + oo];
        size_t base0 = (size_t)(o0 + oo) * HWN + n0 + tx * 4;
        size_t base1 = base0 + 64;
        float4 x0 = *(const float4*)&XR[base0];
        float4 x1 = *(const float4*)&XR[base1];
        float4 r0 = make_float4(x0.x + acc[i][0] + bv_, x0.y + acc[i][1] + bv_,
                                x0.z + acc[i][2] + bv_, x0.w + acc[i][3] + bv_);
        float4 r1 = make_float4(x1.x + acc[i][4] + bv_, x1.y + acc[i][5] + bv_,
                                x1.z + acc[i][6] + bv_, x1.w + acc[i][7] + bv_);
        *(float4*)&OUT[base0] = r0;
        *(float4*)&OUT[base1] = r1;
    }
}

// ---------------- launch ----------------
extern "C" void kernel_launch(void* const* d_in, const int* in_sizes, int n_in,
                              void* d_out, int out_size) {
    const float* x     = (const float*)d_in[0];
    const float* gamma = (const float*)d_in[1];
    const float* beta  = (const float*)d_in[2];
    const float* wq = (const float*)d_in[3]; const float* bq = (const float*)d_in[4];
    const float* wk = (const float*)d_in[5]; const float* bk = (const float*)d_in[6];
    const float* wv = (const float*)d_in[7]; const float* bv = (const float*)d_in[8];
    const float* wp = (const float*)d_in[9]; const float* bp = (const float*)d_in[10];
    float* out = (float*)d_out;

    gn_kernel<<<BB * NG, 256>>>(x, gamma, beta);
    qkv_kernel<<<dim3(HWN / 128, CC / 128, BB * 3), 256>>>(wq, bq, wk, bk, wv, bv);
    scores_kernel<<<dim3(HWN / 128, HWN / 128, BB), 256>>>();
    softmax_kernel<<<BB * HWN, 256>>>();
    av_kernel<<<dim3(HWN / 128, CC / 128, BB), 256>>>();
    proj_kernel<<<dim3(HWN / 128, CC / 128, BB), 256>>>(wp, bp, x, out);
}

// round 2
// speedup vs baseline: 4.9822x; 4.9822x over previous
#include <cuda_runtime.h>
#include <cuda_bf16.h>
#include <cstdint>

typedef __nv_bfloat16 bf16;

#define BB 4
#define CC 512
#define HWN 4096
#define NG 32
#define CPG 16
#define QK_SCALE 0.044194173824159216f  // 1/sqrt(512)
#define PAD 40   // smem pitch in halves for 32-wide K tiles

// ---------------- static scratch ----------------
__device__ bf16  g_hb[(size_t)BB * CC * HWN];   // groupnorm out, [b][c][n]
__device__ bf16  g_ht[(size_t)BB * HWN * CC];   // groupnorm out transposed [b][n][c]
__device__ bf16  g_qt[(size_t)BB * HWN * CC];   // Q^T [b][n][c]
__device__ bf16  g_kt[(size_t)BB * HWN * CC];   // K^T [b][m][c]
__device__ bf16  g_v [(size_t)BB * CC * HWN];   // V   [b][c][m]
__device__ float g_s [(size_t)BB * HWN * HWN];  // scores fp32 [b][n][m]
__device__ bf16  g_sb[(size_t)BB * HWN * HWN];  // attn bf16   [b][n][m]
__device__ bf16  g_ot[(size_t)BB * HWN * CC];   // (attn@V)^T  [b][n][c]
__device__ bf16  g_wb[(size_t)4 * CC * CC];     // wq,wk,wv,wp in bf16

// ---------------- GroupNorm (fp32 in, bf16 out, natural layout) ----------------
__global__ __launch_bounds__(256) void gn_kernel(const float* __restrict__ x,
                                                 const float* __restrict__ gamma,
                                                 const float* __restrict__ beta) {
    int b = blockIdx.x / NG, g = blockIdx.x % NG;
    const float* xp = x + ((size_t)b * CC + (size_t)g * CPG) * HWN;
    bf16* hp = g_hb + ((size_t)b * CC + (size_t)g * CPG) * HWN;
    const int n = CPG * HWN;  // 65536

    float s = 0.f, s2 = 0.f;
    for (int i = threadIdx.x * 4; i < n; i += 1024) {
        float4 v = *(const float4*)&xp[i];
        s  += v.x + v.y + v.z + v.w;
        s2 += v.x * v.x + v.y * v.y + v.z * v.z + v.w * v.w;
    }
    __shared__ float rs[256], rs2[256];
    rs[threadIdx.x] = s; rs2[threadIdx.x] = s2;
    __syncthreads();
    for (int st = 128; st > 0; st >>= 1) {
        if (threadIdx.x < st) {
            rs[threadIdx.x]  += rs[threadIdx.x + st];
            rs2[threadIdx.x] += rs2[threadIdx.x + st];
        }
        __syncthreads();
    }
    float mean = rs[0] / n;
    float var  = rs2[0] / n - mean * mean;
    float inv  = rsqrtf(var + 1e-6f);

    for (int i = threadIdx.x * 4; i < n; i += 1024) {
        int c = g * CPG + (i >> 12);
        float ga = gamma[c], be = beta[c];
        float4 v = *(const float4*)&xp[i];
        __nv_bfloat162 p0 = __floats2bfloat162_rn((v.x - mean) * inv * ga + be,
                                                  (v.y - mean) * inv * ga + be);
        __nv_bfloat162 p1 = __floats2bfloat162_rn((v.z - mean) * inv * ga + be,
                                                  (v.w - mean) * inv * ga + be);
        *(__nv_bfloat162*)&hp[i]     = p0;
        *(__nv_bfloat162*)&hp[i + 2] = p1;
    }
}

// ---------------- transpose g_hb [c][n] -> g_ht [n][c] ----------------
__global__ __launch_bounds__(256) void tr_kernel() {
    __shared__ bf16 t[32][33];
    int b = blockIdx.z;
    int n0 = blockIdx.x * 32, c0 = blockIdx.y * 32;
    const bf16* src = g_hb + (size_t)b * CC * HWN;
    bf16* dst = g_ht + (size_t)b * HWN * CC;
    int tx = threadIdx.x & 31, ty = threadIdx.x >> 5;
#pragma unroll
    for (int r = 0; r < 4; r++)
        t[ty + r * 8][tx] = src[(size_t)(c0 + ty + r * 8) * HWN + n0 + tx];
    __syncthreads();
#pragma unroll
    for (int r = 0; r < 4; r++)
        dst[(size_t)(n0 + ty + r * 8) * CC + c0 + tx] = t[tx][ty + r * 8];
}

// ---------------- weight fp32 -> bf16 ----------------
__global__ __launch_bounds__(256) void wconv_kernel(const float* __restrict__ wq,
                                                    const float* __restrict__ wk,
                                                    const float* __restrict__ wv,
                                                    const float* __restrict__ wp) {
    const float* srcs[4] = {wq, wk, wv, wp};
    int m = blockIdx.y;
    int idx = blockIdx.x * 256 + threadIdx.x;  // float4 index
    float4 v = *(const float4*)&srcs[m][idx * 4];
    bf16* dst = g_wb + (size_t)m * CC * CC + idx * 4;
    *(__nv_bfloat162*)&dst[0] = __floats2bfloat162_rn(v.x, v.y);
    *(__nv_bfloat162*)&dst[2] = __floats2bfloat162_rn(v.z, v.w);
}

// ---------------- mma helpers ----------------
__device__ __forceinline__ uint32_t smem_u32(const void* p) {
    return (uint32_t)__cvta_generic_to_shared(p);
}
__device__ __forceinline__ void ldmx4(uint32_t addr, uint32_t& r0, uint32_t& r1,
                                      uint32_t& r2, uint32_t& r3) {
    asm volatile("ldmatrix.sync.aligned.m8n8.x4.shared.b16 {%0,%1,%2,%3}, [%4];"
                 : "=r"(r0), "=r"(r1), "=r"(r2), "=r"(r3) : "r"(addr));
}
__device__ __forceinline__ void mma16816(float c[4], uint32_t a0, uint32_t a1, uint32_t a2,
                                         uint32_t a3, uint32_t b0, uint32_t b1) {
    asm volatile(
        "mma.sync.aligned.m16n8k16.row.col.f32.bf16.bf16.f32 "
        "{%0,%1,%2,%3}, {%4,%5,%6,%7}, {%8,%9}, {%0,%1,%2,%3};"
        : "+f"(c[0]), "+f"(c[1]), "+f"(c[2]), "+f"(c[3])
        : "r"(a0), "r"(a1), "r"(a2), "r"(a3), "r"(b0), "r"(b1));
}

// ---------------- GEMM core: C[128][128] (i x j), K-major bf16 operands ----------------
// C[i][j] = sum_k A[i][k] * B[j][k]
// EPI 0: bf16 direct + bias     EPI 1: fp32 direct * scale
// EPI 2: bf16 transposed (+bias)  EPI 3: fp32 + bias + residual
template <int EPI>
__device__ __forceinline__ void gemm_core(unsigned char* sm,
                                          const bf16* __restrict__ A, int lda,
                                          const bf16* __restrict__ B, int ldb, int K,
                                          void* Cg, int ldc,
                                          const float* __restrict__ bias, float scale,
                                          const float* __restrict__ resid,
                                          int i0, int j0) {
    bf16* As = (bf16*)sm;                 // [128][PAD]
    bf16* Bs = As + 128 * PAD;            // [128][PAD]
    int tid = threadIdx.x, lane = tid & 31, wid = tid >> 5;
    int wm = wid >> 1, wn = wid & 1;

    float acc[2][8][4];
#pragma unroll
    for (int mi = 0; mi < 2; mi++)
#pragma unroll
        for (int ni = 0; ni < 8; ni++)
#pragma unroll
            for (int r = 0; r < 4; r++) acc[mi][ni][r] = 0.f;

    int lr = tid >> 2, lc = (tid & 3) * 8;
    const bf16* Ag  = A + (size_t)(i0 + lr) * lda + lc;
    const bf16* Ag2 = Ag + (size_t)64 * lda;
    const bf16* Bg  = B + (size_t)(j0 + lr) * ldb + lc;
    const bf16* Bg2 = Bg + (size_t)64 * ldb;

    int am_row = wm * 32 + (lane & 15);
    int a_kh   = (lane >> 4) * 8;
    uint32_t aAddr = smem_u32(&As[am_row * PAD + a_kh]);
    int b_nl  = (lane & 7) + ((lane >> 4) << 3);
    int b_sel = ((lane >> 3) & 1) * 8;
    uint32_t bAddr = smem_u32(&Bs[(wn * 64 + b_nl) * PAD + b_sel]);

    for (int kk = 0; kk < K; kk += 32) {
        uint4 va0 = *(const uint4*)(Ag + kk);
        uint4 va1 = *(const uint4*)(Ag2 + kk);
        uint4 vb0 = *(const uint4*)(Bg + kk);
        uint4 vb1 = *(const uint4*)(Bg2 + kk);
        __syncthreads();
        *(uint4*)&As[lr * PAD + lc]        = va0;
        *(uint4*)&As[(lr + 64) * PAD + lc] = va1;
        *(uint4*)&Bs[lr * PAD + lc]        = vb0;
        *(uint4*)&Bs[(lr + 64) * PAD + lc] = vb1;
        __syncthreads();
#pragma unroll
        for (int ks = 0; ks < 32; ks += 16) {
            uint32_t af[2][4];
#pragma unroll
            for (int mi = 0; mi < 2; mi++)
                ldmx4(aAddr + (mi * 16 * PAD + ks) * 2,
                      af[mi][0], af[mi][1], af[mi][2], af[mi][3]);
            uint32_t bf4[4][4];
#pragma unroll
            for (int nq = 0; nq < 4; nq++)
                ldmx4(bAddr + (nq * 16 * PAD + ks) * 2,
                      bf4[nq][0], bf4[nq][1], bf4[nq][2], bf4[nq][3]);
#pragma unroll
            for (int mi = 0; mi < 2; mi++)
#pragma unroll
                for (int ni = 0; ni < 8; ni++)
                    mma16816(acc[mi][ni], af[mi][0], af[mi][1], af[mi][2], af[mi][3],
                             bf4[ni >> 1][(ni & 1) * 2], bf4[ni >> 1][(ni & 1) * 2 + 1]);
        }
    }

    int g = lane >> 2, t = lane & 3;

    if (EPI == 0) {  // bf16 direct + bias (row-indexed)
        bf16* C = (bf16*)Cg;
#pragma unroll
        for (int mi = 0; mi < 2; mi++) {
            int r0 = wm * 32 + mi * 16 + g;
            float bv0 = bias ? bias[i0 + r0] : 0.f;
            float bv8 = bias ? bias[i0 + r0 + 8] : 0.f;
#pragma unroll
            for (int ni = 0; ni < 8; ni++) {
                int col = j0 + wn * 64 + ni * 8 + 2 * t;
                *(__nv_bfloat162*)&C[(size_t)(i0 + r0) * ldc + col] =
                    __floats2bfloat162_rn(acc[mi][ni][0] + bv0, acc[mi][ni][1] + bv0);
                *(__nv_bfloat162*)&C[(size_t)(i0 + r0 + 8) * ldc + col] =
                    __floats2bfloat162_rn(acc[mi][ni][2] + bv8, acc[mi][ni][3] + bv8);
            }
        }
    } else if (EPI == 1) {  // fp32 direct * scale
        float* C = (float*)Cg;
#pragma unroll
        for (int mi = 0; mi < 2; mi++) {
            int r0 = wm * 32 + mi * 16 + g;
#pragma unroll
            for (int ni = 0; ni < 8; ni++) {
                int col = j0 + wn * 64 + ni * 8 + 2 * t;
                float2 p0 = make_float2(acc[mi][ni][0] * scale, acc[mi][ni][1] * scale);
                float2 p1 = make_float2(acc[mi][ni][2] * scale, acc[mi][ni][3] * scale);
                *(float2*)&C[(size_t)(i0 + r0) * ldc + col]     = p0;
                *(float2*)&C[(size_t)(i0 + r0 + 8) * ldc + col] = p1;
            }
        }
    } else if (EPI == 2) {  // bf16 transposed via smem (+bias on i-dim)
        __syncthreads();
        bf16* Ct = (bf16*)sm;  // [j 128][i pitch 136]
#pragma unroll
        for (int mi = 0; mi < 2; mi++) {
            int r = wm * 32 + mi * 16 + g;
            float bv0 = bias ? bias[i0 + r] : 0.f;
            float bv8 = bias ? bias[i0 + r + 8] : 0.f;
#pragma unroll
            for (int ni = 0; ni < 8; ni++) {
                int c = wn * 64 + ni * 8 + 2 * t;
                Ct[(size_t)c * 136 + r]           = __float2bfloat16(acc[mi][ni][0] + bv0);
                Ct[(size_t)(c + 1) * 136 + r]     = __float2bfloat16(acc[mi][ni][1] + bv0);
                Ct[(size_t)c * 136 + r + 8]       = __float2bfloat16(acc[mi][ni][2] + bv8);
                Ct[(size_t)(c + 1) * 136 + r + 8] = __float2bfloat16(acc[mi][ni][3] + bv8);
            }
        }
        __syncthreads();
        int j = tid >> 1, h = tid & 1;
        bf16* Crow = (bf16*)Cg + (size_t)(j0 + j) * ldc + i0 + h * 64;
        const bf16* Srow = Ct + (size_t)j * 136 + h * 64;
#pragma unroll
        for (int q = 0; q < 8; q++)
            *(uint4*)(Crow + q * 8) = *(const uint4*)(Srow + q * 8);
    } else {  // EPI 3: fp32 + bias + residual
        float* C = (float*)Cg;
#pragma unroll
        for (int mi = 0; mi < 2; mi++) {
            int r0 = wm * 32 + mi * 16 + g;
            float bv0 = bias[i0 + r0];
            float bv8 = bias[i0 + r0 + 8];
#pragma unroll
            for (int ni = 0; ni < 8; ni++) {
                int col = j0 + wn * 64 + ni * 8 + 2 * t;
                size_t o0 = (size_t)(i0 + r0) * ldc + col;
                size_t o8 = (size_t)(i0 + r0 + 8) * ldc + col;
                float2 x0 = *(const float2*)&resid[o0];
                float2 x8 = *(const float2*)&resid[o8];
                *(float2*)&C[o0] = make_float2(acc[mi][ni][0] + bv0 + x0.x,
                                               acc[mi][ni][1] + bv0 + x0.y);
                *(float2*)&C[o8] = make_float2(acc[mi][ni][2] + bv8 + x8.x,
                                               acc[mi][ni][3] + bv8 + x8.y);
            }
        }
    }
}

// ---------------- GEMM wrappers ----------------
__global__ __launch_bounds__(256) void gemm_qkv_kernel(const float* __restrict__ bq,
                                                       const float* __restrict__ bk,
                                                       const float* __restrict__ bv) {
    __shared__ __align__(16) unsigned char sm[34816];
    int z = blockIdx.z, b = z / 3, m = z % 3;
    const bf16* A = g_wb + (size_t)m * CC * CC;
    const bf16* B = g_ht + (size_t)b * HWN * CC;
    int i0 = blockIdx.y * 128, j0 = blockIdx.x * 128;
    if (m == 0)
        gemm_core<2>(sm, A, CC, B, CC, CC, g_qt + (size_t)b * HWN * CC, CC, bq, 1.f, nullptr, i0, j0);
    else if (m == 1)
        gemm_core<2>(sm, A, CC, B, CC, CC, g_kt + (size_t)b * HWN * CC, CC, bk, 1.f, nullptr, i0, j0);
    else
        gemm_core<0>(sm, A, CC, B, CC, CC, g_v + (size_t)b * CC * HWN, HWN, bv, 1.f, nullptr, i0, j0);
}

__global__ __launch_bounds__(256) void gemm_scores_kernel() {
    __shared__ __align__(16) unsigned char sm[34816];
    int b = blockIdx.z;
    int i0 = blockIdx.y * 128, j0 = blockIdx.x * 128;
    gemm_core<1>(sm, g_qt + (size_t)b * HWN * CC, CC, g_kt + (size_t)b * HWN * CC, CC, CC,
                 g_s + (size_t)b * HWN * HWN, HWN, nullptr, QK_SCALE, nullptr, i0, j0);
}

__global__ __launch_bounds__(256) void gemm_av_kernel() {
    __shared__ __align__(16) unsigned char sm[34816];
    int b = blockIdx.z;
    int i0 = blockIdx.y * 128, j0 = blockIdx.x * 128;  // i over c, j over n
    gemm_core<2>(sm, g_v + (size_t)b * CC * HWN, HWN, g_sb + (size_t)b * HWN * HWN, HWN, HWN,
                 g_ot + (size_t)b * HWN * CC, CC, nullptr, 1.f, nullptr, i0, j0);
}

__global__ __launch_bounds__(256) void gemm_proj_kernel(const float* __restrict__ bp,
                                                        const float* __restrict__ x,
                                                        float* __restrict__ out) {
    __shared__ __align__(16) unsigned char sm[34816];
    int b = blockIdx.z;
    int i0 = blockIdx.y * 128, j0 = blockIdx.x * 128;  // i over o(c), j over n
    gemm_core<3>(sm, g_wb + (size_t)3 * CC * CC, CC, g_ot + (size_t)b * HWN * CC, CC, CC,
                 out + (size_t)b * CC * HWN, HWN, bp, 1.f, x + (size_t)b * CC * HWN, i0, j0);
}

// ---------------- softmax: fp32 in (g_s), bf16 out (g_sb) ----------------
__global__ __launch_bounds__(256) void softmax_kernel() {
    const float* row = g_s + (size_t)blockIdx.x * HWN;
    bf16* drow = g_sb + (size_t)blockIdx.x * HWN;
    int tid = threadIdx.x;

    float4 vals[4];
    float mx = -1e30f;
#pragma unroll
    for (int i = 0; i < 4; i++) {
        vals[i] = *(const float4*)&row[i * 1024 + tid * 4];
        mx = fmaxf(mx, fmaxf(fmaxf(vals[i].x, vals[i].y), fmaxf(vals[i].z, vals[i].w)));
    }
    __shared__ float red[256];
    red[tid] = mx; __syncthreads();
    for (int st = 128; st > 0; st >>= 1) {
        if (tid < st) red[tid] = fmaxf(red[tid], red[tid + st]);
        __syncthreads();
    }
    mx = red[0];
    __syncthreads();

    float sum = 0.f;
#pragma unroll
    for (int i = 0; i < 4; i++) {
        vals[i].x = __expf(vals[i].x - mx);
        vals[i].y = __expf(vals[i].y - mx);
        vals[i].z = __expf(vals[i].z - mx);
        vals[i].w = __expf(vals[i].w - mx);
        sum += vals[i].x + vals[i].y + vals[i].z + vals[i].w;
    }
    red[tid] = sum; __syncthreads();
    for (int st = 128; st > 0; st >>= 1) {
        if (tid < st) red[tid] += red[tid + st];
        __syncthreads();
    }
    float inv = 1.0f / red[0];

#pragma unroll
    for (int i = 0; i < 4; i++) {
        int e = i * 1024 + tid * 4;
        *(__nv_bfloat162*)&drow[e]     = __floats2bfloat162_rn(vals[i].x * inv, vals[i].y * inv);
        *(__nv_bfloat162*)&drow[e + 2] = __floats2bfloat162_rn(vals[i].z * inv, vals[i].w * inv);
    }
}

// ---------------- launch ----------------
extern "C" void kernel_launch(void* const* d_in, const int* in_sizes, int n_in,
                              void* d_out, int out_size) {
    const float* x     = (const float*)d_in[0];
    const float* gamma = (const float*)d_in[1];
    const float* beta  = (const float*)d_in[2];
    const float* wq = (const float*)d_in[3]; const float* bq = (const float*)d_in[4];
    const float* wk = (const float*)d_in[5]; const float* bk = (const float*)d_in[6];
    const float* wv = (const float*)d_in[7]; const float* bv = (const float*)d_in[8];
    const float* wp = (const float*)d_in[9]; const float* bp = (const float*)d_in[10];
    float* out = (float*)d_out;

    gn_kernel<<<BB * NG, 256>>>(x, gamma, beta);
    tr_kernel<<<dim3(HWN / 32, CC / 32, BB), 256>>>();
    wconv_kernel<<<dim3(CC * CC / 4 / 256, 4), 256>>>(wq, wk, wv, wp);
    gemm_qkv_kernel<<<dim3(HWN / 128, CC / 128, BB * 3), 256>>>(bq, bk, bv);
    gemm_scores_kernel<<<dim3(HWN / 128, HWN / 128, BB), 256>>>();
    softmax_kernel<<<BB * HWN, 256>>>();
    gemm_av_kernel<<<dim3(HWN / 128, CC / 128, BB), 256>>>();
    gemm_proj_kernel<<<dim3(HWN / 128, CC / 128, BB), 256>>>(bp, x, out);
}

// round 3
// speedup vs baseline: 6.2464x; 1.2537x over previous
#include <cuda_runtime.h>
#include <cuda_bf16.h>
#include <cstdint>

typedef __nv_bfloat16 bf16;

#define BB 4
#define CC 512
#define HWN 4096
#define NG 32
#define CPG 16
#define QK_SCALE 0.044194173824159216f  // 1/sqrt(512)
#define PAD 40                           // smem pitch (halves) for 32-wide K tiles
#define STAGES 3
#define OP_BYTES (128 * PAD * 2)         // one operand, one stage = 10240 B
#define STAGE_BYTES (2 * OP_BYTES)       // A + B per stage = 20480 B
#define SMEM_TOTAL (STAGES * STAGE_BYTES)  // 61440 B

// ---------------- static scratch ----------------
__device__ float g_stats[BB * NG * 2];          // mean, inv per (b, group)
__device__ bf16  g_ht[(size_t)BB * HWN * CC];   // normed H^T [b][n][c]
__device__ bf16  g_qt[(size_t)BB * HWN * CC];   // Q^T [b][n][c]
__device__ bf16  g_kt[(size_t)BB * HWN * CC];   // K^T [b][m][c]
__device__ bf16  g_v [(size_t)BB * CC * HWN];   // V   [b][c][m]
__device__ bf16  g_sb[(size_t)BB * HWN * HWN];  // scores/attn bf16 [b][n][m]
__device__ bf16  g_ot[(size_t)BB * HWN * CC];   // (attn@V)^T [b][n][c]
__device__ bf16  g_wb[(size_t)4 * CC * CC];     // wq,wk,wv,wp bf16

// ---------------- GroupNorm stats ----------------
__global__ __launch_bounds__(256) void gn_stats_kernel(const float* __restrict__ x) {
    int b = blockIdx.x / NG, g = blockIdx.x % NG;
    const float* xp = x + ((size_t)b * CC + (size_t)g * CPG) * HWN;
    const int n = CPG * HWN;  // 65536

    float s = 0.f, s2 = 0.f;
    for (int i = threadIdx.x * 4; i < n; i += 1024) {
        float4 v = *(const float4*)&xp[i];
        s  += v.x + v.y + v.z + v.w;
        s2 += v.x * v.x + v.y * v.y + v.z * v.z + v.w * v.w;
    }
    __shared__ float rs[256], rs2[256];
    rs[threadIdx.x] = s; rs2[threadIdx.x] = s2;
    __syncthreads();
    for (int st = 128; st > 0; st >>= 1) {
        if (threadIdx.x < st) {
            rs[threadIdx.x]  += rs[threadIdx.x + st];
            rs2[threadIdx.x] += rs2[threadIdx.x + st];
        }
        __syncthreads();
    }
    if (threadIdx.x == 0) {
        float mean = rs[0] / n;
        float var  = rs2[0] / n - mean * mean;
        g_stats[blockIdx.x * 2]     = mean;
        g_stats[blockIdx.x * 2 + 1] = rsqrtf(var + 1e-6f);
    }
}

// ---------------- norm + transpose: x [c][n] fp32 -> g_ht [n][c] bf16 ----------------
__global__ __launch_bounds__(256) void trn_kernel(const float* __restrict__ x,
                                                  const float* __restrict__ gamma,
                                                  const float* __restrict__ beta) {
    __shared__ float t[32][33];
    int b = blockIdx.z;
    int n0 = blockIdx.x * 32, c0 = blockIdx.y * 32;
    const float* src = x + (size_t)b * CC * HWN;
    bf16* dst = g_ht + (size_t)b * HWN * CC;
    int tx = threadIdx.x & 31, ty = threadIdx.x >> 5;
#pragma unroll
    for (int r = 0; r < 4; r++) {
        int c = c0 + ty + r * 8;
        float mean = g_stats[(b * NG + c / CPG) * 2];
        float inv  = g_stats[(b * NG + c / CPG) * 2 + 1];
        float v = src[(size_t)c * HWN + n0 + tx];
        t[ty + r * 8][tx] = (v - mean) * inv * gamma[c] + beta[c];
    }
    __syncthreads();
#pragma unroll
    for (int r = 0; r < 4; r++)
        dst[(size_t)(n0 + ty + r * 8) * CC + c0 + tx] = __float2bfloat16(t[tx][ty + r * 8]);
}

// ---------------- weight fp32 -> bf16 ----------------
__global__ __launch_bounds__(256) void wconv_kernel(const float* __restrict__ wq,
                                                    const float* __restrict__ wk,
                                                    const float* __restrict__ wv,
                                                    const float* __restrict__ wp) {
    const float* srcs[4] = {wq, wk, wv, wp};
    int m = blockIdx.y;
    int idx = blockIdx.x * 256 + threadIdx.x;
    float4 v = *(const float4*)&srcs[m][idx * 4];
    bf16* dst = g_wb + (size_t)m * CC * CC + idx * 4;
    *(__nv_bfloat162*)&dst[0] = __floats2bfloat162_rn(v.x, v.y);
    *(__nv_bfloat162*)&dst[2] = __floats2bfloat162_rn(v.z, v.w);
}

// ---------------- mma helpers ----------------
__device__ __forceinline__ uint32_t smem_u32(const void* p) {
    return (uint32_t)__cvta_generic_to_shared(p);
}
__device__ __forceinline__ void cp16(uint32_t d, const void* s) {
    asm volatile("cp.async.cg.shared.global [%0], [%1], 16;" :: "r"(d), "l"(s));
}
__device__ __forceinline__ void ldmx4(uint32_t addr, uint32_t& r0, uint32_t& r1,
                                      uint32_t& r2, uint32_t& r3) {
    asm volatile("ldmatrix.sync.aligned.m8n8.x4.shared.b16 {%0,%1,%2,%3}, [%4];"
                 : "=r"(r0), "=r"(r1), "=r"(r2), "=r"(r3) : "r"(addr));
}
__device__ __forceinline__ void mma16816(float c[4], uint32_t a0, uint32_t a1, uint32_t a2,
                                         uint32_t a3, uint32_t b0, uint32_t b1) {
    asm volatile(
        "mma.sync.aligned.m16n8k16.row.col.f32.bf16.bf16.f32 "
        "{%0,%1,%2,%3}, {%4,%5,%6,%7}, {%8,%9}, {%0,%1,%2,%3};"
        : "+f"(c[0]), "+f"(c[1]), "+f"(c[2]), "+f"(c[3])
        : "r"(a0), "r"(a1), "r"(a2), "r"(a3), "r"(b0), "r"(b1));
}

// ---------------- GEMM core: C[i 128][j 128] = sum_k A[i][k] B[j][k], 3-stage cp.async ----
// EPI 0: bf16 direct, *scale, +bias(optional)
// EPI 2: bf16 transposed via smem, +bias(optional)
// EPI 3: fp32 + bias + residual
template <int EPI>
__device__ __forceinline__ void gemm_core(unsigned char* sm,
                                          const bf16* __restrict__ A, int lda,
                                          const bf16* __restrict__ B, int ldb, int K,
                                          void* Cg, int ldc,
                                          const float* __restrict__ bias, float scale,
                                          const float* __restrict__ resid,
                                          int i0, int j0) {
    int tid = threadIdx.x, lane = tid & 31, wid = tid >> 5;
    int wm = wid >> 1, wn = wid & 1;

    float acc[2][8][4];
#pragma unroll
    for (int mi = 0; mi < 2; mi++)
#pragma unroll
        for (int ni = 0; ni < 8; ni++)
#pragma unroll
            for (int r = 0; r < 4; r++) acc[mi][ni][r] = 0.f;

    int lr = tid >> 2, lc = (tid & 3) * 8;
    const bf16* Ag  = A + (size_t)(i0 + lr) * lda + lc;
    const bf16* Ag2 = Ag + (size_t)64 * lda;
    const bf16* Bg  = B + (size_t)(j0 + lr) * ldb + lc;
    const bf16* Bg2 = Bg + (size_t)64 * ldb;

    uint32_t smBase = smem_u32(sm);
    uint32_t wOff = smBase + (lr * PAD + lc) * 2;

    // ldmatrix source addresses (stage 0)
    int am_row = wm * 32 + (lane & 15);
    int a_kh   = (lane >> 4) * 8;
    uint32_t aAddr = smBase + (am_row * PAD + a_kh) * 2;
    int b_nl  = (lane & 7) + ((lane >> 4) << 3);
    int b_sel = ((lane >> 3) & 1) * 8;
    uint32_t bAddr = smBase + OP_BYTES + ((wn * 64 + b_nl) * PAD + b_sel) * 2;

    const int nK = K / 32;

    // prologue: stages 0 .. STAGES-2
#pragma unroll
    for (int s = 0; s < STAGES - 1; s++) {
        uint32_t d = wOff + s * STAGE_BYTES;
        cp16(d,                      Ag  + s * 32);
        cp16(d + 64 * PAD * 2,       Ag2 + s * 32);
        cp16(d + OP_BYTES,           Bg  + s * 32);
        cp16(d + OP_BYTES + 64 * PAD * 2, Bg2 + s * 32);
        asm volatile("cp.async.commit_group;");
    }

    for (int kt = 0; kt < nK; kt++) {
        asm volatile("cp.async.wait_group 1;" ::: "memory");
        __syncthreads();

        int pf = kt + STAGES - 1;
        if (pf < nK) {
            uint32_t d = wOff + (pf % STAGES) * STAGE_BYTES;
            cp16(d,                      Ag  + pf * 32);
            cp16(d + 64 * PAD * 2,       Ag2 + pf * 32);
            cp16(d + OP_BYTES,           Bg  + pf * 32);
            cp16(d + OP_BYTES + 64 * PAD * 2, Bg2 + pf * 32);
        }
        asm volatile("cp.async.commit_group;");

        uint32_t stOff = (kt % STAGES) * STAGE_BYTES;
#pragma unroll
        for (int ks = 0; ks < 32; ks += 16) {
            uint32_t af[2][4];
#pragma unroll
            for (int mi = 0; mi < 2; mi++)
                ldmx4(aAddr + stOff + (mi * 16 * PAD + ks) * 2,
                      af[mi][0], af[mi][1], af[mi][2], af[mi][3]);
            uint32_t bf4[4][4];
#pragma unroll
            for (int nq = 0; nq < 4; nq++)
                ldmx4(bAddr + stOff + (nq * 16 * PAD + ks) * 2,
                      bf4[nq][0], bf4[nq][1], bf4[nq][2], bf4[nq][3]);
#pragma unroll
            for (int mi = 0; mi < 2; mi++)
#pragma unroll
                for (int ni = 0; ni < 8; ni++)
                    mma16816(acc[mi][ni], af[mi][0], af[mi][1], af[mi][2], af[mi][3],
                             bf4[ni >> 1][(ni & 1) * 2], bf4[ni >> 1][(ni & 1) * 2 + 1]);
        }
    }

    int g = lane >> 2, t = lane & 3;

    if (EPI == 0) {  // bf16 direct, *scale, +bias
        bf16* C = (bf16*)Cg;
#pragma unroll
        for (int mi = 0; mi < 2; mi++) {
            int r0 = wm * 32 + mi * 16 + g;
            float bv0 = bias ? bias[i0 + r0] : 0.f;
            float bv8 = bias ? bias[i0 + r0 + 8] : 0.f;
#pragma unroll
            for (int ni = 0; ni < 8; ni++) {
                int col = j0 + wn * 64 + ni * 8 + 2 * t;
                *(__nv_bfloat162*)&C[(size_t)(i0 + r0) * ldc + col] =
                    __floats2bfloat162_rn(acc[mi][ni][0] * scale + bv0,
                                          acc[mi][ni][1] * scale + bv0);
                *(__nv_bfloat162*)&C[(size_t)(i0 + r0 + 8) * ldc + col] =
                    __floats2bfloat162_rn(acc[mi][ni][2] * scale + bv8,
                                          acc[mi][ni][3] * scale + bv8);
            }
        }
    } else if (EPI == 2) {  // bf16 transposed via smem (+bias on i-dim)
        __syncthreads();
        bf16* Ct = (bf16*)sm;  // [j 128][i pitch 136]
#pragma unroll
        for (int mi = 0; mi < 2; mi++) {
            int r = wm * 32 + mi * 16 + g;
            float bv0 = bias ? bias[i0 + r] : 0.f;
            float bv8 = bias ? bias[i0 + r + 8] : 0.f;
#pragma unroll
            for (int ni = 0; ni < 8; ni++) {
                int c = wn * 64 + ni * 8 + 2 * t;
                Ct[(size_t)c * 136 + r]           = __float2bfloat16(acc[mi][ni][0] + bv0);
                Ct[(size_t)(c + 1) * 136 + r]     = __float2bfloat16(acc[mi][ni][1] + bv0);
                Ct[(size_t)c * 136 + r + 8]       = __float2bfloat16(acc[mi][ni][2] + bv8);
                Ct[(size_t)(c + 1) * 136 + r + 8] = __float2bfloat16(acc[mi][ni][3] + bv8);
            }
        }
        __syncthreads();
        int j = tid >> 1, h = tid & 1;
        bf16* Crow = (bf16*)Cg + (size_t)(j0 + j) * ldc + i0 + h * 64;
        const bf16* Srow = Ct + (size_t)j * 136 + h * 64;
#pragma unroll
        for (int q = 0; q < 8; q++)
            *(uint4*)(Crow + q * 8) = *(const uint4*)(Srow + q * 8);
    } else {  // EPI 3: fp32 + bias + residual
        float* C = (float*)Cg;
#pragma unroll
        for (int mi = 0; mi < 2; mi++) {
            int r0 = wm * 32 + mi * 16 + g;
            float bv0 = bias[i0 + r0];
            float bv8 = bias[i0 + r0 + 8];
#pragma unroll
            for (int ni = 0; ni < 8; ni++) {
                int col = j0 + wn * 64 + ni * 8 + 2 * t;
                size_t o0 = (size_t)(i0 + r0) * ldc + col;
                size_t o8 = (size_t)(i0 + r0 + 8) * ldc + col;
                float2 x0 = *(const float2*)&resid[o0];
                float2 x8 = *(const float2*)&resid[o8];
                *(float2*)&C[o0] = make_float2(acc[mi][ni][0] + bv0 + x0.x,
                                               acc[mi][ni][1] + bv0 + x0.y);
                *(float2*)&C[o8] = make_float2(acc[mi][ni][2] + bv8 + x8.x,
                                               acc[mi][ni][3] + bv8 + x8.y);
            }
        }
    }
}

// ---------------- GEMM wrappers (dynamic smem) ----------------
extern __shared__ unsigned char dyn_sm[];

__global__ __launch_bounds__(256, 2) void gemm_qkv_kernel(const float* __restrict__ bq,
                                                          const float* __restrict__ bk,
                                                          const float* __restrict__ bv) {
    int z = blockIdx.z, b = z / 3, m = z % 3;
    const bf16* A = g_wb + (size_t)m * CC * CC;
    const bf16* B = g_ht + (size_t)b * HWN * CC;
    int i0 = blockIdx.y * 128, j0 = blockIdx.x * 128;
    if (m == 0)
        gemm_core<2>(dyn_sm, A, CC, B, CC, CC, g_qt + (size_t)b * HWN * CC, CC, bq, 1.f, nullptr, i0, j0);
    else if (m == 1)
        gemm_core<2>(dyn_sm, A, CC, B, CC, CC, g_kt + (size_t)b * HWN * CC, CC, bk, 1.f, nullptr, i0, j0);
    else
        gemm_core<0>(dyn_sm, A, CC, B, CC, CC, g_v + (size_t)b * CC * HWN, HWN, bv, 1.f, nullptr, i0, j0);
}

__global__ __launch_bounds__(256, 2) void gemm_scores_kernel() {
    int b = blockIdx.z;
    int i0 = blockIdx.y * 128, j0 = blockIdx.x * 128;
    gemm_core<0>(dyn_sm, g_qt + (size_t)b * HWN * CC, CC, g_kt + (size_t)b * HWN * CC, CC, CC,
                 g_sb + (size_t)b * HWN * HWN, HWN, nullptr, QK_SCALE, nullptr, i0, j0);
}

__global__ __launch_bounds__(256, 2) void gemm_av_kernel() {
    int b = blockIdx.z;
    int i0 = blockIdx.y * 128, j0 = blockIdx.x * 128;  // i over c, j over n
    gemm_core<2>(dyn_sm, g_v + (size_t)b * CC * HWN, HWN, g_sb + (size_t)b * HWN * HWN, HWN, HWN,
                 g_ot + (size_t)b * HWN * CC, CC, nullptr, 1.f, nullptr, i0, j0);
}

__global__ __launch_bounds__(256, 2) void gemm_proj_kernel(const float* __restrict__ bp,
                                                           const float* __restrict__ x,
                                                           float* __restrict__ out) {
    int b = blockIdx.z;
    int i0 = blockIdx.y * 128, j0 = blockIdx.x * 128;  // i over o(c), j over n
    gemm_core<3>(dyn_sm, g_wb + (size_t)3 * CC * CC, CC, g_ot + (size_t)b * HWN * CC, CC, CC,
                 out + (size_t)b * CC * HWN, HWN, bp, 1.f, x + (size_t)b * CC * HWN, i0, j0);
}

// ---------------- softmax: bf16 in place (g_sb) ----------------
__global__ __launch_bounds__(256) void softmax_kernel() {
    bf16* row = g_sb + (size_t)blockIdx.x * HWN;
    int tid = threadIdx.x;

    // 16 halves per thread = 2 x uint4
    float v[16];
#pragma unroll
    for (int u = 0; u < 2; u++) {
        uint4 pk = *(const uint4*)&row[tid * 16 + u * 8];
        const __nv_bfloat162* h2 = (const __nv_bfloat162*)&pk;
#pragma unroll
        for (int e = 0; e < 4; e++) {
            float2 f = __bfloat1622float2(h2[e]);
            v[u * 8 + e * 2]     = f.x;
            v[u * 8 + e * 2 + 1] = f.y;
        }
    }
    float mx = -1e30f;
#pragma unroll
    for (int e = 0; e < 16; e++) mx = fmaxf(mx, v[e]);

    __shared__ float red[256];
    red[tid] = mx; __syncthreads();
    for (int st = 128; st > 0; st >>= 1) {
        if (tid < st) red[tid] = fmaxf(red[tid], red[tid + st]);
        __syncthreads();
    }
    mx = red[0];
    __syncthreads();

    float sum = 0.f;
#pragma unroll
    for (int e = 0; e < 16; e++) {
        v[e] = __expf(v[e] - mx);
        sum += v[e];
    }
    red[tid] = sum; __syncthreads();
    for (int st = 128; st > 0; st >>= 1) {
        if (tid < st) red[tid] += red[tid + st];
        __syncthreads();
    }
    float inv = 1.0f / red[0];

#pragma unroll
    for (int u = 0; u < 2; u++) {
        uint4 pk;
        __nv_bfloat162* h2 = (__nv_bfloat162*)&pk;
#pragma unroll
        for (int e = 0; e < 4; e++)
            h2[e] = __floats2bfloat162_rn(v[u * 8 + e * 2] * inv, v[u * 8 + e * 2 + 1] * inv);
        *(uint4*)&row[tid * 16 + u * 8] = pk;
    }
}

// ---------------- launch ----------------
extern "C" void kernel_launch(void* const* d_in, const int* in_sizes, int n_in,
                              void* d_out, int out_size) {
    const float* x     = (const float*)d_in[0];
    const float* gamma = (const float*)d_in[1];
    const float* beta  = (const float*)d_in[2];
    const float* wq = (const float*)d_in[3]; const float* bq = (const float*)d_in[4];
    const float* wk = (const float*)d_in[5]; const float* bk = (const float*)d_in[6];
    const float* wv = (const float*)d_in[7]; const float* bv = (const float*)d_in[8];
    const float* wp = (const float*)d_in[9]; const float* bp = (const float*)d_in[10];
    float* out = (float*)d_out;

    static bool attr_done = false;
    if (!attr_done) {
        cudaFuncSetAttribute(gemm_qkv_kernel,    cudaFuncAttributeMaxDynamicSharedMemorySize, SMEM_TOTAL);
        cudaFuncSetAttribute(gemm_scores_kernel, cudaFuncAttributeMaxDynamicSharedMemorySize, SMEM_TOTAL);
        cudaFuncSetAttribute(gemm_av_kernel,     cudaFuncAttributeMaxDynamicSharedMemorySize, SMEM_TOTAL);
        cudaFuncSetAttribute(gemm_proj_kernel,   cudaFuncAttributeMaxDynamicSharedMemorySize, SMEM_TOTAL);
        attr_done = true;
    }

    gn_stats_kernel<<<BB * NG, 256>>>(x);
    trn_kernel<<<dim3(HWN / 32, CC / 32, BB), 256>>>(x, gamma, beta);
    wconv_kernel<<<dim3(CC * CC / 4 / 256, 4), 256>>>(wq, wk, wv, wp);
    gemm_qkv_kernel<<<dim3(HWN / 128, CC / 128, BB * 3), 256, SMEM_TOTAL>>>(bq, bk, bv);
    gemm_scores_kernel<<<dim3(HWN / 128, HWN / 128, BB), 256, SMEM_TOTAL>>>();
    softmax_kernel<<<BB * HWN, 256>>>();
    gemm_av_kernel<<<dim3(HWN / 128, CC / 128, BB), 256, SMEM_TOTAL>>>();
    gemm_proj_kernel<<<dim3(HWN / 128, CC / 128, BB), 256, SMEM_TOTAL>>>(bp, x, out);
}